// round 14
// baseline (speedup 1.0000x reference)
#include <cuda_runtime.h>
#include <cuda_fp16.h>
#include <cstdint>

#define N_NODES 50000
#define N_PAD   50048
#define N_EDGES 800000
#define HID 64
#define N_CLS 16
#define MAX_DEG 64

// Scratch (device globals — no allocation allowed)
__device__ int    g_cnt[N_NODES];
__device__ int    g_adj[N_NODES * MAX_DEG];
__device__ __align__(16) __half g_xh[N_PAD * HID];     // x as half (padded, tail 0)
__device__ __align__(16) __half g_meanh[N_PAD * HID];  // mean as half (padded, tail 0)
__device__ __align__(16) __half g_h[N_PAD * HID];      // layer-1 output, half (padded)
__device__ __align__(16) float  g_p[N_PAD * N_CLS];    // h @ W2_l, fp32 (padded)
__device__ __align__(16) float  g_pm[N_PAD * N_CLS];   // mean of p, fp32 (padded)
// Weights pre-packed into m16n8k16 B-fragment register order:
//   index = ((kc * NT + nt) * 32 + lane) * 2 + r
__device__ __align__(16) uint32_t g_w1p[8 * 8 * 32 * 2];   // [kc8][nt8][lane][2]
__device__ __align__(16) uint32_t g_w2lp[4 * 2 * 32 * 2];  // [kc4][nt2][lane][2]
__device__ __align__(16) uint32_t g_w2rp[4 * 2 * 32 * 2];

__device__ __forceinline__ uint32_t h2pack(float a, float b) {
    __half2 h = __floats2half2_rn(a, b);
    return *reinterpret_cast<uint32_t*>(&h);
}

__device__ __forceinline__ void mma16816(float& c0, float& c1, float& c2, float& c3,
                                         uint32_t a0, uint32_t a1, uint32_t a2, uint32_t a3,
                                         uint32_t b0, uint32_t b1) {
    asm volatile("mma.sync.aligned.m16n8k16.row.col.f32.f16.f16.f32 "
                 "{%0,%1,%2,%3}, {%4,%5,%6,%7}, {%8,%9}, {%0,%1,%2,%3};"
                 : "+f"(c0), "+f"(c1), "+f"(c2), "+f"(c3)
                 : "r"(a0), "r"(a1), "r"(a2), "r"(a3), "r"(b0), "r"(b1));
}

// ---------------------------------------------------------------------------
// Init: zero counters; x->half (+pad zero); pack weights into fragment order.
// B-frag m16n8k16: reg r holds halves (k = kc*16 + t*2 + 8r, k+1), n = nt*8 + g.
// ---------------------------------------------------------------------------
__global__ void init_k(const float* __restrict__ x,
                       const float* __restrict__ W1l, const float* __restrict__ W1r,
                       const float* __restrict__ W2l, const float* __restrict__ W2r) {
    int i = blockIdx.x * blockDim.x + threadIdx.x;
    if (i < N_NODES) g_cnt[i] = 0;
    if (i < 4096) {
        int kc = i >> 9, nt = (i >> 6) & 7, lane = (i >> 1) & 31, r = i & 1;
        int gq = lane >> 2, tq = lane & 3;
        int k = kc * 16 + tq * 2 + r * 8;
        int n = nt * 8 + gq;
        float w0 = (k < 64) ? W1l[k * 64 + n] : W1r[(k - 64) * 64 + n];
        float w1 = (k + 1 < 64) ? W1l[(k + 1) * 64 + n] : W1r[(k + 1 - 64) * 64 + n];
        g_w1p[i] = h2pack(w0, w1);
    }
    if (i < 512) {
        int kc = i >> 7, nt = (i >> 6) & 1, lane = (i >> 1) & 31, r = i & 1;
        int gq = lane >> 2, tq = lane & 3;
        int k = kc * 16 + tq * 2 + r * 8;
        int n = nt * 8 + gq;
        g_w2lp[i] = h2pack(W2l[k * 16 + n], W2l[(k + 1) * 16 + n]);
        g_w2rp[i] = h2pack(W2r[k * 16 + n], W2r[(k + 1) * 16 + n]);
    }
    if (i < N_PAD * HID) {
        int node = i >> 6;
        if (node < N_NODES) {
            g_xh[i] = __float2half_rn(x[i]);
        } else {
            g_xh[i]    = __float2half_rn(0.f);
            g_meanh[i] = __float2half_rn(0.f);
        }
    }
}

__global__ void fill_k(const int* __restrict__ ei) {
    int e = blockIdx.x * blockDim.x + threadIdx.x;
    if (e >= N_EDGES) return;
    int s = ei[e];
    int d = ei[N_EDGES + e];
    if ((unsigned)s >= N_NODES || (unsigned)d >= N_NODES) return;
    int pos = atomicAdd(&g_cnt[d], 1);
    if (pos < MAX_DEG) g_adj[d * MAX_DEG + pos] = s;
}

// ---------------------------------------------------------------------------
// Mean gather over half rows: 16 threads/node (2 slots x 8 uint4-lanes).
// ---------------------------------------------------------------------------
__global__ void gather_mean_x_k() {
    int t = blockIdx.x * blockDim.x + threadIdx.x;
    int node = t >> 4;
    int sub  = t & 15;
    int g    = sub >> 3;
    int f    = sub & 7;
    if (node >= N_NODES) return;
    int c = g_cnt[node];
    int cl = min(c, MAX_DEG);
    const int4* row4 = reinterpret_cast<const int4*>(g_adj + (size_t)node * MAX_DEG);
    const uint4* src = reinterpret_cast<const uint4*>(g_xh);

    float2 a[4] = {{0.f,0.f},{0.f,0.f},{0.f,0.f},{0.f,0.f}};
    float2 b[4] = {{0.f,0.f},{0.f,0.f},{0.f,0.f},{0.f,0.f}};
    int nfull = cl >> 2;
#pragma unroll 2
    for (int j4 = 0; j4 < nfull; j4++) {
        int4 idx = __ldg(row4 + j4);
        int i0 = g ? idx.z : idx.x;
        int i1 = g ? idx.w : idx.y;
        uint4 v0 = __ldg(src + ((size_t)i0 << 3) + f);
        uint4 v1 = __ldg(src + ((size_t)i1 << 3) + f);
        const __half2* h0 = reinterpret_cast<const __half2*>(&v0);
        const __half2* h1 = reinterpret_cast<const __half2*>(&v1);
#pragma unroll
        for (int q = 0; q < 4; q++) {
            float2 f0 = __half22float2(h0[q]);
            float2 f1 = __half22float2(h1[q]);
            a[q].x += f0.x; a[q].y += f0.y;
            b[q].x += f1.x; b[q].y += f1.y;
        }
    }
    for (int j = nfull * 4 + g; j < cl; j += 2) {
        int s = __ldg(g_adj + (size_t)node * MAX_DEG + j);
        uint4 v = __ldg(src + ((size_t)s << 3) + f);
        const __half2* h = reinterpret_cast<const __half2*>(&v);
#pragma unroll
        for (int q = 0; q < 4; q++) {
            float2 fv = __half22float2(h[q]);
            a[q].x += fv.x; a[q].y += fv.y;
        }
    }
    float r[8];
#pragma unroll
    for (int q = 0; q < 4; q++) {
        r[q * 2]     = a[q].x + b[q].x;
        r[q * 2 + 1] = a[q].y + b[q].y;
    }
#pragma unroll
    for (int q = 0; q < 8; q++)
        r[q] += __shfl_xor_sync(0xffffffff, r[q], 8);
    if (g == 0) {
        float invd = 1.0f / fmaxf((float)c, 1.0f);
        uint4 o;
        __half2* oh = reinterpret_cast<__half2*>(&o);
#pragma unroll
        for (int q = 0; q < 4; q++)
            oh[q] = __floats2half2_rn(r[q * 2] * invd, r[q * 2 + 1] * invd);
        reinterpret_cast<uint4*>(g_meanh)[((size_t)node << 3) + f] = o;
    }
}

// ---------------------------------------------------------------------------
// p-mean gather (fp32): 8 threads/node (2 slots x 4 f4-lanes).
// ---------------------------------------------------------------------------
__global__ void gather_mean_p_k() {
    int t = blockIdx.x * blockDim.x + threadIdx.x;
    int node = t >> 3;
    int sub  = t & 7;
    int g    = sub >> 2;
    int f    = sub & 3;
    if (node >= N_NODES) return;
    int c = g_cnt[node];
    int cl = min(c, MAX_DEG);
    const int4* row4 = reinterpret_cast<const int4*>(g_adj + (size_t)node * MAX_DEG);
    const float4* src = reinterpret_cast<const float4*>(g_p);
    float4 a0 = make_float4(0.f,0.f,0.f,0.f), a1 = a0;
    int nfull = cl >> 2;
#pragma unroll 2
    for (int j4 = 0; j4 < nfull; j4++) {
        int4 idx = __ldg(row4 + j4);
        int i0 = g ? idx.z : idx.x;
        int i1 = g ? idx.w : idx.y;
        float4 v0 = __ldg(src + ((size_t)i0 << 2) + f);
        float4 v1 = __ldg(src + ((size_t)i1 << 2) + f);
        a0.x += v0.x; a0.y += v0.y; a0.z += v0.z; a0.w += v0.w;
        a1.x += v1.x; a1.y += v1.y; a1.z += v1.z; a1.w += v1.w;
    }
    for (int j = nfull * 4 + g; j < cl; j += 2) {
        int s = __ldg(g_adj + (size_t)node * MAX_DEG + j);
        float4 v = __ldg(src + ((size_t)s << 2) + f);
        a0.x += v.x; a0.y += v.y; a0.z += v.z; a0.w += v.w;
    }
    float4 r;
    r.x = a0.x + a1.x; r.y = a0.y + a1.y; r.z = a0.z + a1.z; r.w = a0.w + a1.w;
    r.x += __shfl_xor_sync(0xffffffff, r.x, 4);
    r.y += __shfl_xor_sync(0xffffffff, r.y, 4);
    r.z += __shfl_xor_sync(0xffffffff, r.z, 4);
    r.w += __shfl_xor_sync(0xffffffff, r.w, 4);
    if (g == 0) {
        float invd = 1.0f / fmaxf((float)c, 1.0f);
        r.x *= invd; r.y *= invd; r.z *= invd; r.w *= invd;
        reinterpret_cast<float4*>(g_pm)[((size_t)node << 2) + f] = r;
    }
}

// ---------------------------------------------------------------------------
// Layer 1: raw mma, zero smem, zero syncs. Warp owns 16 rows.
//   h = relu([mean||x] @ W1 + b1);  p = h @ W2l
// acc(n-tile pair) re-packs directly into the next GEMM's A fragment.
// ---------------------------------------------------------------------------
__global__ void __launch_bounds__(128)
layer1_k(const float* __restrict__ b1) {
    int tid = threadIdx.x, warp = tid >> 5, lane = tid & 31;
    int g = lane >> 2, t = lane & 3;
    int row0 = blockIdx.x * 64 + warp * 16;

    const __half* mrow = g_meanh + (size_t)(row0 + g) * 64;
    const __half* xrow = g_xh    + (size_t)(row0 + g) * 64;

    // Load all A fragments (8 k-chunks x 4 regs) — max MLP, rows padded
    uint32_t A[8][4];
#pragma unroll
    for (int kc = 0; kc < 8; kc++) {
        const __half* base = (kc < 4) ? (mrow + kc * 16) : (xrow + (kc - 4) * 16);
        A[kc][0] = *reinterpret_cast<const uint32_t*>(base + t * 2);
        A[kc][1] = *reinterpret_cast<const uint32_t*>(base + 8 * 64 + t * 2);
        A[kc][2] = *reinterpret_cast<const uint32_t*>(base + t * 2 + 8);
        A[kc][3] = *reinterpret_cast<const uint32_t*>(base + 8 * 64 + t * 2 + 8);
    }

    // GEMM1 per n-tile, epilogue in-register -> H (h as half2 pieces)
    uint32_t H[8][2];
#pragma unroll
    for (int nt = 0; nt < 8; nt++) {
        float c0 = 0.f, c1 = 0.f, c2 = 0.f, c3 = 0.f;
#pragma unroll
        for (int kc = 0; kc < 8; kc++) {
            const uint32_t* bp = g_w1p + ((kc * 8 + nt) * 32 + lane) * 2;
            mma16816(c0, c1, c2, c3, A[kc][0], A[kc][1], A[kc][2], A[kc][3], bp[0], bp[1]);
        }
        float2 bias = *reinterpret_cast<const float2*>(b1 + nt * 8 + t * 2);
        c0 = fmaxf(c0 + bias.x, 0.f);
        c1 = fmaxf(c1 + bias.y, 0.f);
        c2 = fmaxf(c2 + bias.x, 0.f);
        c3 = fmaxf(c3 + bias.y, 0.f);
        H[nt][0] = h2pack(c0, c1);   // row g,   cols nt*8 + 2t, +1
        H[nt][1] = h2pack(c2, c3);   // row g+8, cols nt*8 + 2t, +1
    }

    // Store h (g_h padded -> unguarded, coalesced-ish STG.32)
    __half* hr0 = g_h + (size_t)(row0 + g) * 64;
    __half* hr8 = hr0 + 8 * 64;
#pragma unroll
    for (int nt = 0; nt < 8; nt++) {
        *reinterpret_cast<uint32_t*>(hr0 + nt * 8 + t * 2) = H[nt][0];
        *reinterpret_cast<uint32_t*>(hr8 + nt * 8 + t * 2) = H[nt][1];
    }

    // GEMM2: p = h @ W2l (N=16 -> 2 n-tiles, K=64 -> 4 k-chunks).
    // A fragment of k-chunk kc = acc tiles (2kc, 2kc+1) re-packed: exact layout match.
#pragma unroll
    for (int nt = 0; nt < 2; nt++) {
        float c0 = 0.f, c1 = 0.f, c2 = 0.f, c3 = 0.f;
#pragma unroll
        for (int kc = 0; kc < 4; kc++) {
            const uint32_t* bp = g_w2lp + ((kc * 2 + nt) * 32 + lane) * 2;
            mma16816(c0, c1, c2, c3,
                     H[2 * kc][0], H[2 * kc][1], H[2 * kc + 1][0], H[2 * kc + 1][1],
                     bp[0], bp[1]);
        }
        float* pr = g_p + (size_t)(row0 + g) * 16 + nt * 8 + t * 2;
        *reinterpret_cast<float2*>(pr)          = make_float2(c0, c1);
        *reinterpret_cast<float2*>(pr + 8 * 16) = make_float2(c2, c3);
    }
}

// ---------------------------------------------------------------------------
// Final: raw mma, zero smem. out = g_pm + h @ W2r + b2.
// ---------------------------------------------------------------------------
__global__ void __launch_bounds__(128)
final_k(const float* __restrict__ b2, float* __restrict__ out) {
    int tid = threadIdx.x, warp = tid >> 5, lane = tid & 31;
    int g = lane >> 2, t = lane & 3;
    int row0 = blockIdx.x * 64 + warp * 16;

    const __half* hrow = g_h + (size_t)(row0 + g) * 64;
    uint32_t A[4][4];
#pragma unroll
    for (int kc = 0; kc < 4; kc++) {
        A[kc][0] = *reinterpret_cast<const uint32_t*>(hrow + kc * 16 + t * 2);
        A[kc][1] = *reinterpret_cast<const uint32_t*>(hrow + 8 * 64 + kc * 16 + t * 2);
        A[kc][2] = *reinterpret_cast<const uint32_t*>(hrow + kc * 16 + t * 2 + 8);
        A[kc][3] = *reinterpret_cast<const uint32_t*>(hrow + 8 * 64 + kc * 16 + t * 2 + 8);
    }

    int r0 = row0 + g, r8 = r0 + 8;
#pragma unroll
    for (int nt = 0; nt < 2; nt++) {
        float c0 = 0.f, c1 = 0.f, c2 = 0.f, c3 = 0.f;
#pragma unroll
        for (int kc = 0; kc < 4; kc++) {
            const uint32_t* bp = g_w2rp + ((kc * 2 + nt) * 32 + lane) * 2;
            mma16816(c0, c1, c2, c3, A[kc][0], A[kc][1], A[kc][2], A[kc][3], bp[0], bp[1]);
        }
        float2 bias = *reinterpret_cast<const float2*>(b2 + nt * 8 + t * 2);
        int col = nt * 8 + t * 2;
        if (r0 < N_NODES) {
            float2 pm = *reinterpret_cast<const float2*>(g_pm + (size_t)r0 * 16 + col);
            *reinterpret_cast<float2*>(out + (size_t)r0 * 16 + col) =
                make_float2(c0 + bias.x + pm.x, c1 + bias.y + pm.y);
        }
        if (r8 < N_NODES) {
            float2 pm = *reinterpret_cast<const float2*>(g_pm + (size_t)r8 * 16 + col);
            *reinterpret_cast<float2*>(out + (size_t)r8 * 16 + col) =
                make_float2(c2 + bias.x + pm.x, c3 + bias.y + pm.y);
        }
    }
}

// ---------------------------------------------------------------------------
extern "C" void kernel_launch(void* const* d_in, const int* in_sizes, int n_in,
                              void* d_out, int out_size) {
    const float* x   = (const float*)d_in[0];
    const int*   ei  = (const int*)d_in[1];     // int32 (JAX x64 disabled)
    const float* W1l = (const float*)d_in[2];
    const float* b1  = (const float*)d_in[3];
    const float* W1r = (const float*)d_in[4];
    const float* W2l = (const float*)d_in[5];
    const float* b2  = (const float*)d_in[6];
    const float* W2r = (const float*)d_in[7];
    float* out = (float*)d_out;

    const int NBLK = (N_NODES + 63) / 64;   // 782

    init_k<<<(N_PAD * HID + 255) / 256, 256>>>(x, W1l, W1r, W2l, W2r);
    fill_k<<<(N_EDGES + 255) / 256, 256>>>(ei);
    gather_mean_x_k<<<(N_NODES * 16 + 255) / 256, 256>>>();
    layer1_k<<<NBLK, 128>>>(b1);
    gather_mean_p_k<<<(N_NODES * 8 + 255) / 256, 256>>>();
    final_k<<<NBLK, 128>>>(b2, out);
}

// round 15
// speedup vs baseline: 1.4782x; 1.4782x over previous
#include <cuda_runtime.h>
#include <cuda_fp16.h>
#include <cstdint>

#define N_NODES 50000
#define N_PAD   50048
#define N_EDGES 800000
#define HID 64
#define N_CLS 16
#define MAX_DEG 64

// Scratch (device globals — zero-initialized at module load; pad rows of
// g_xh/g_meanh/g_h are never written so they stay zero forever)
__device__ int    g_cnt[N_NODES];
__device__ int    g_adj[N_NODES * MAX_DEG];
__device__ __align__(16) __half g_xh[N_PAD * HID];
__device__ __align__(16) __half g_meanh[N_PAD * HID];
__device__ __align__(16) __half g_h[N_PAD * HID];
__device__ __align__(16) float  g_p[N_PAD * N_CLS];
__device__ __align__(16) float  g_pm[N_PAD * N_CLS];
// Weights pre-packed into m16n8k16 B-fragment register order:
//   index = ((kc * NT + nt) * 32 + lane) * 2 + r
__device__ __align__(16) uint32_t g_w1p[8 * 8 * 32 * 2];
__device__ __align__(16) uint32_t g_w2lp[4 * 2 * 32 * 2];
__device__ __align__(16) uint32_t g_w2rp[4 * 2 * 32 * 2];

__device__ __forceinline__ uint32_t h2pack(float a, float b) {
    __half2 h = __floats2half2_rn(a, b);
    return *reinterpret_cast<uint32_t*>(&h);
}

__device__ __forceinline__ void mma16816(float* c,
                                         uint32_t a0, uint32_t a1, uint32_t a2, uint32_t a3,
                                         uint32_t b0, uint32_t b1) {
    asm volatile("mma.sync.aligned.m16n8k16.row.col.f32.f16.f16.f32 "
                 "{%0,%1,%2,%3}, {%4,%5,%6,%7}, {%8,%9}, {%0,%1,%2,%3};"
                 : "+f"(c[0]), "+f"(c[1]), "+f"(c[2]), "+f"(c[3])
                 : "r"(a0), "r"(a1), "r"(a2), "r"(a3), "r"(b0), "r"(b1));
}

// ---------------------------------------------------------------------------
// Setup: zero degree counters + pack weights into fragment order. Tiny.
// ---------------------------------------------------------------------------
__global__ void setup_k(const float* __restrict__ W1l, const float* __restrict__ W1r,
                        const float* __restrict__ W2l, const float* __restrict__ W2r) {
    int i = blockIdx.x * blockDim.x + threadIdx.x;
    if (i < N_NODES) g_cnt[i] = 0;
    if (i < 4096) {
        int kc = i >> 9, nt = (i >> 6) & 7, lane = (i >> 1) & 31, r = i & 1;
        int gq = lane >> 2, tq = lane & 3;
        int k = kc * 16 + tq * 2 + r * 8;
        int n = nt * 8 + gq;
        float w0 = (k < 64) ? W1l[k * 64 + n] : W1r[(k - 64) * 64 + n];
        float w1 = (k + 1 < 64) ? W1l[(k + 1) * 64 + n] : W1r[(k + 1 - 64) * 64 + n];
        g_w1p[i] = h2pack(w0, w1);
    }
    if (i < 512) {
        int kc = i >> 7, nt = (i >> 6) & 1, lane = (i >> 1) & 31, r = i & 1;
        int gq = lane >> 2, tq = lane & 3;
        int k = kc * 16 + tq * 2 + r * 8;
        int n = nt * 8 + gq;
        g_w2lp[i] = h2pack(W2l[k * 16 + n], W2l[(k + 1) * 16 + n]);
        g_w2rp[i] = h2pack(W2r[k * 16 + n], W2r[(k + 1) * 16 + n]);
    }
}

// ---------------------------------------------------------------------------
// Prep: adjacency fill FUSED with x->half conversion (independent work,
// overlaps atomic latency with streaming conversion).
// ---------------------------------------------------------------------------
__global__ void prep_k(const int* __restrict__ ei, const float* __restrict__ x) {
    int i = blockIdx.x * blockDim.x + threadIdx.x;
    if (i < N_EDGES) {
        int s = ei[i];
        int d = ei[N_EDGES + i];
        if ((unsigned)s < N_NODES && (unsigned)d < N_NODES) {
            int pos = atomicAdd(&g_cnt[d], 1);
            if (pos < MAX_DEG) g_adj[d * MAX_DEG + pos] = s;
        }
    }
    if (i < N_NODES * HID / 2) {
        float2 v = reinterpret_cast<const float2*>(x)[i];
        reinterpret_cast<__half2*>(g_xh)[i] = __floats2half2_rn(v.x, v.y);
    }
}

// ---------------------------------------------------------------------------
// Mean gather over half rows: 16 threads/node (2 slots x 8 uint4-lanes).
// ---------------------------------------------------------------------------
__global__ void gather_mean_x_k() {
    int t = blockIdx.x * blockDim.x + threadIdx.x;
    int node = t >> 4;
    int sub  = t & 15;
    int g    = sub >> 3;
    int f    = sub & 7;
    if (node >= N_NODES) return;
    int c = g_cnt[node];
    int cl = min(c, MAX_DEG);
    const int4* row4 = reinterpret_cast<const int4*>(g_adj + (size_t)node * MAX_DEG);
    const uint4* src = reinterpret_cast<const uint4*>(g_xh);

    float2 a[4] = {{0.f,0.f},{0.f,0.f},{0.f,0.f},{0.f,0.f}};
    float2 b[4] = {{0.f,0.f},{0.f,0.f},{0.f,0.f},{0.f,0.f}};
    int nfull = cl >> 2;
#pragma unroll 2
    for (int j4 = 0; j4 < nfull; j4++) {
        int4 idx = __ldg(row4 + j4);
        int i0 = g ? idx.z : idx.x;
        int i1 = g ? idx.w : idx.y;
        uint4 v0 = __ldg(src + ((size_t)i0 << 3) + f);
        uint4 v1 = __ldg(src + ((size_t)i1 << 3) + f);
        const __half2* h0 = reinterpret_cast<const __half2*>(&v0);
        const __half2* h1 = reinterpret_cast<const __half2*>(&v1);
#pragma unroll
        for (int q = 0; q < 4; q++) {
            float2 f0 = __half22float2(h0[q]);
            float2 f1 = __half22float2(h1[q]);
            a[q].x += f0.x; a[q].y += f0.y;
            b[q].x += f1.x; b[q].y += f1.y;
        }
    }
    for (int j = nfull * 4 + g; j < cl; j += 2) {
        int s = __ldg(g_adj + (size_t)node * MAX_DEG + j);
        uint4 v = __ldg(src + ((size_t)s << 3) + f);
        const __half2* h = reinterpret_cast<const __half2*>(&v);
#pragma unroll
        for (int q = 0; q < 4; q++) {
            float2 fv = __half22float2(h[q]);
            a[q].x += fv.x; a[q].y += fv.y;
        }
    }
    float r[8];
#pragma unroll
    for (int q = 0; q < 4; q++) {
        r[q * 2]     = a[q].x + b[q].x;
        r[q * 2 + 1] = a[q].y + b[q].y;
    }
#pragma unroll
    for (int q = 0; q < 8; q++)
        r[q] += __shfl_xor_sync(0xffffffff, r[q], 8);
    if (g == 0) {
        float invd = 1.0f / fmaxf((float)c, 1.0f);
        uint4 o;
        __half2* oh = reinterpret_cast<__half2*>(&o);
#pragma unroll
        for (int q = 0; q < 4; q++)
            oh[q] = __floats2half2_rn(r[q * 2] * invd, r[q * 2 + 1] * invd);
        reinterpret_cast<uint4*>(g_meanh)[((size_t)node << 3) + f] = o;
    }
}

// ---------------------------------------------------------------------------
// p-mean gather (fp32): 8 threads/node (2 slots x 4 f4-lanes).
// ---------------------------------------------------------------------------
__global__ void gather_mean_p_k() {
    int t = blockIdx.x * blockDim.x + threadIdx.x;
    int node = t >> 3;
    int sub  = t & 7;
    int g    = sub >> 2;
    int f    = sub & 3;
    if (node >= N_NODES) return;
    int c = g_cnt[node];
    int cl = min(c, MAX_DEG);
    const int4* row4 = reinterpret_cast<const int4*>(g_adj + (size_t)node * MAX_DEG);
    const float4* src = reinterpret_cast<const float4*>(g_p);
    float4 a0 = make_float4(0.f,0.f,0.f,0.f), a1 = a0;
    int nfull = cl >> 2;
#pragma unroll 2
    for (int j4 = 0; j4 < nfull; j4++) {
        int4 idx = __ldg(row4 + j4);
        int i0 = g ? idx.z : idx.x;
        int i1 = g ? idx.w : idx.y;
        float4 v0 = __ldg(src + ((size_t)i0 << 2) + f);
        float4 v1 = __ldg(src + ((size_t)i1 << 2) + f);
        a0.x += v0.x; a0.y += v0.y; a0.z += v0.z; a0.w += v0.w;
        a1.x += v1.x; a1.y += v1.y; a1.z += v1.z; a1.w += v1.w;
    }
    for (int j = nfull * 4 + g; j < cl; j += 2) {
        int s = __ldg(g_adj + (size_t)node * MAX_DEG + j);
        float4 v = __ldg(src + ((size_t)s << 2) + f);
        a0.x += v.x; a0.y += v.y; a0.z += v.z; a0.w += v.w;
    }
    float4 r;
    r.x = a0.x + a1.x; r.y = a0.y + a1.y; r.z = a0.z + a1.z; r.w = a0.w + a1.w;
    r.x += __shfl_xor_sync(0xffffffff, r.x, 4);
    r.y += __shfl_xor_sync(0xffffffff, r.y, 4);
    r.z += __shfl_xor_sync(0xffffffff, r.z, 4);
    r.w += __shfl_xor_sync(0xffffffff, r.w, 4);
    if (g == 0) {
        float invd = 1.0f / fmaxf((float)c, 1.0f);
        r.x *= invd; r.y *= invd; r.z *= invd; r.w *= invd;
        reinterpret_cast<float4*>(g_pm)[((size_t)node << 2) + f] = r;
    }
}

// ---------------------------------------------------------------------------
// Layer 1: raw mma, zero smem/syncs, 2 m-tiles (32 rows) per warp.
// B-fragment loads shared across both tiles (halves W1 L1 traffic).
// ---------------------------------------------------------------------------
__global__ void __launch_bounds__(128)
layer1_k(const float* __restrict__ b1) {
    int tid = threadIdx.x, warp = tid >> 5, lane = tid & 31;
    int g = lane >> 2, t = lane & 3;
    int row0 = (blockIdx.x * 4 + warp) * 32;

    // A fragments for both tiles (rows padded -> unguarded)
    uint32_t A[2][8][4];
#pragma unroll
    for (int m = 0; m < 2; m++) {
        const __half* mrow = g_meanh + (size_t)(row0 + m * 16 + g) * 64;
        const __half* xrow = g_xh    + (size_t)(row0 + m * 16 + g) * 64;
#pragma unroll
        for (int kc = 0; kc < 8; kc++) {
            const __half* base = (kc < 4) ? (mrow + kc * 16) : (xrow + (kc - 4) * 16);
            A[m][kc][0] = *reinterpret_cast<const uint32_t*>(base + t * 2);
            A[m][kc][1] = *reinterpret_cast<const uint32_t*>(base + 8 * 64 + t * 2);
            A[m][kc][2] = *reinterpret_cast<const uint32_t*>(base + t * 2 + 8);
            A[m][kc][3] = *reinterpret_cast<const uint32_t*>(base + 8 * 64 + t * 2 + 8);
        }
    }

    // GEMM1: shared B per (kc,nt), two MMAs
    uint32_t H[2][8][2];
#pragma unroll
    for (int nt = 0; nt < 8; nt++) {
        float c[2][4] = {{0.f,0.f,0.f,0.f},{0.f,0.f,0.f,0.f}};
#pragma unroll
        for (int kc = 0; kc < 8; kc++) {
            uint2 b = *reinterpret_cast<const uint2*>(g_w1p + ((kc * 8 + nt) * 32 + lane) * 2);
#pragma unroll
            for (int m = 0; m < 2; m++)
                mma16816(c[m], A[m][kc][0], A[m][kc][1], A[m][kc][2], A[m][kc][3], b.x, b.y);
        }
        float2 bias = *reinterpret_cast<const float2*>(b1 + nt * 8 + t * 2);
#pragma unroll
        for (int m = 0; m < 2; m++) {
            H[m][nt][0] = h2pack(fmaxf(c[m][0] + bias.x, 0.f), fmaxf(c[m][1] + bias.y, 0.f));
            H[m][nt][1] = h2pack(fmaxf(c[m][2] + bias.x, 0.f), fmaxf(c[m][3] + bias.y, 0.f));
        }
    }

    // Store h + GEMM2 per tile
#pragma unroll
    for (int m = 0; m < 2; m++) {
        __half* hr0 = g_h + (size_t)(row0 + m * 16 + g) * 64;
        __half* hr8 = hr0 + 8 * 64;
#pragma unroll
        for (int nt = 0; nt < 8; nt++) {
            *reinterpret_cast<uint32_t*>(hr0 + nt * 8 + t * 2) = H[m][nt][0];
            *reinterpret_cast<uint32_t*>(hr8 + nt * 8 + t * 2) = H[m][nt][1];
        }
#pragma unroll
        for (int nt = 0; nt < 2; nt++) {
            float c[4] = {0.f, 0.f, 0.f, 0.f};
#pragma unroll
            for (int kc = 0; kc < 4; kc++) {
                uint2 b = *reinterpret_cast<const uint2*>(g_w2lp + ((kc * 2 + nt) * 32 + lane) * 2);
                mma16816(c, H[m][2 * kc][0], H[m][2 * kc][1],
                            H[m][2 * kc + 1][0], H[m][2 * kc + 1][1], b.x, b.y);
            }
            float* pr = g_p + (size_t)(row0 + m * 16 + g) * 16 + nt * 8 + t * 2;
            *reinterpret_cast<float2*>(pr)          = make_float2(c[0], c[1]);
            *reinterpret_cast<float2*>(pr + 8 * 16) = make_float2(c[2], c[3]);
        }
    }
}

// ---------------------------------------------------------------------------
// Final: raw mma, zero smem. out = g_pm + h @ W2r + b2.
// ---------------------------------------------------------------------------
__global__ void __launch_bounds__(128)
final_k(const float* __restrict__ b2, float* __restrict__ out) {
    int tid = threadIdx.x, warp = tid >> 5, lane = tid & 31;
    int g = lane >> 2, t = lane & 3;
    int row0 = blockIdx.x * 64 + warp * 16;

    const __half* hrow = g_h + (size_t)(row0 + g) * 64;
    uint32_t A[4][4];
#pragma unroll
    for (int kc = 0; kc < 4; kc++) {
        A[kc][0] = *reinterpret_cast<const uint32_t*>(hrow + kc * 16 + t * 2);
        A[kc][1] = *reinterpret_cast<const uint32_t*>(hrow + 8 * 64 + kc * 16 + t * 2);
        A[kc][2] = *reinterpret_cast<const uint32_t*>(hrow + kc * 16 + t * 2 + 8);
        A[kc][3] = *reinterpret_cast<const uint32_t*>(hrow + 8 * 64 + kc * 16 + t * 2 + 8);
    }

    int r0 = row0 + g, r8 = r0 + 8;
#pragma unroll
    for (int nt = 0; nt < 2; nt++) {
        float c[4] = {0.f, 0.f, 0.f, 0.f};
#pragma unroll
        for (int kc = 0; kc < 4; kc++) {
            uint2 b = *reinterpret_cast<const uint2*>(g_w2rp + ((kc * 2 + nt) * 32 + lane) * 2);
            mma16816(c, A[kc][0], A[kc][1], A[kc][2], A[kc][3], b.x, b.y);
        }
        float2 bias = *reinterpret_cast<const float2*>(b2 + nt * 8 + t * 2);
        int col = nt * 8 + t * 2;
        if (r0 < N_NODES) {
            float2 pm = *reinterpret_cast<const float2*>(g_pm + (size_t)r0 * 16 + col);
            *reinterpret_cast<float2*>(out + (size_t)r0 * 16 + col) =
                make_float2(c[0] + bias.x + pm.x, c[1] + bias.y + pm.y);
        }
        if (r8 < N_NODES) {
            float2 pm = *reinterpret_cast<const float2*>(g_pm + (size_t)r8 * 16 + col);
            *reinterpret_cast<float2*>(out + (size_t)r8 * 16 + col) =
                make_float2(c[2] + bias.x + pm.x, c[3] + bias.y + pm.y);
        }
    }
}

// ---------------------------------------------------------------------------
extern "C" void kernel_launch(void* const* d_in, const int* in_sizes, int n_in,
                              void* d_out, int out_size) {
    const float* x   = (const float*)d_in[0];
    const int*   ei  = (const int*)d_in[1];     // int32 (JAX x64 disabled)
    const float* W1l = (const float*)d_in[2];
    const float* b1  = (const float*)d_in[3];
    const float* W1r = (const float*)d_in[4];
    const float* W2l = (const float*)d_in[5];
    const float* b2  = (const float*)d_in[6];
    const float* W2r = (const float*)d_in[7];
    float* out = (float*)d_out;

    setup_k<<<(N_NODES + 255) / 256, 256>>>(W1l, W1r, W2l, W2r);
    prep_k<<<(N_NODES * HID / 2 + 255) / 256, 256>>>(ei, x);
    gather_mean_x_k<<<(N_NODES * 16 + 255) / 256, 256>>>();
    layer1_k<<<N_PAD / 128, 128>>>(b1);                 // 391 blocks, 32 rows/warp
    gather_mean_p_k<<<(N_NODES * 8 + 255) / 256, 256>>>();
    final_k<<<N_PAD / 64, 128>>>(b2, out);              // 782 blocks
}